// round 7
// baseline (speedup 1.0000x reference)
#include <cuda_runtime.h>

#define CRF_B 128
#define CRF_S 1024
#define CRF_T 128
#define CRF_SOS 0
#define CRF_EOS 1
#define NT 256
#define PPAD 136   // p vector: half A at [0,64), half B at [68,132) -> conflict-free 2-addr broadcast

typedef unsigned long long u64;

__device__ float g_part[CRF_B];
__device__ int   g_count;          // zero-initialized; reset by the reducing CTA each run

__device__ __forceinline__ u64 pack2(float lo, float hi) {
    u64 r; asm("mov.b64 %0,{%1,%2};" : "=l"(r) : "f"(lo), "f"(hi)); return r;
}
__device__ __forceinline__ u64 fma2(u64 a, u64 b, u64 c) {
    u64 d; asm("fma.rn.f32x2 %0,%1,%2,%3;" : "=l"(d) : "l"(a), "l"(b), "l"(c)); return d;
}
__device__ __forceinline__ u64 add2(u64 a, u64 b) {
    u64 d; asm("add.rn.f32x2 %0,%1,%2;" : "=l"(d) : "l"(a), "l"(b)); return d;
}
__device__ __forceinline__ void unpack2(u64 v, float& lo, float& hi) {
    asm("mov.b64 {%0,%1},%2;" : "=f"(lo), "=f"(hi) : "l"(v));
}

// One CRF step, split-K by 2 inside each warp (lanes 0-15 = half A, 16-31 = half B).
// Halves combine with a single shfl.bfly(16); one __syncthreads per step.
// APPLY: fold renorm scale published last step (red_sm pre-seeded to 1.0 => no-op first time);
//        scale path is independent of the dot product -> overlapped by the scheduler.
// PUBLISH: CTA max of pnew via warp REDUX (p>=0 -> fp32 max == u32 bit-pattern max).
template<bool APPLY, bool PUBLISH>
__device__ __forceinline__ void crf_step(
    float (*p_sm)[PPAD], float* red_sm, const u64* Ereg,
    int& buf, float& pcur, float& Ccum,
    float eexp_t, float m, int pidx, int h, int w, int lane)
{
    const ulonglong2* pq = (const ulonglong2*)(p_sm[buf] + h * 68);
    u64 a0 = 0, a1 = 0, a2 = 0, a3 = 0;
#pragma unroll
    for (int k = 0; k < 16; k += 2) {           // 16 x LDS.128, 32 x fma2
        ulonglong2 q0 = pq[k];
        ulonglong2 q1 = pq[k + 1];
        a0 = fma2(q0.x, Ereg[2 * k + 0], a0);
        a1 = fma2(q0.y, Ereg[2 * k + 1], a1);
        a2 = fma2(q1.x, Ereg[2 * k + 2], a2);
        a3 = fma2(q1.y, Ereg[2 * k + 3], a3);
    }

    float ee = eexp_t;          // pre-scaled in APPLY steps
    float pc = pcur;
    if (APPLY) {                // alpha = log(p) + Ccum preserved exactly
        float M = red_sm[0];
#pragma unroll
        for (int r = 1; r < 8; ++r) M = fmaxf(M, red_sm[r]);
        float inv = 1.0f / M;
        Ccum += __logf(M);
        ee = inv * eexp_t;
        pc = inv * pcur;
    }

    u64 s2 = add2(add2(a0, a1), add2(a2, a3));
    float slo, shi;
    unpack2(s2, slo, shi);
    float sh = slo + shi;
    sh += __shfl_xor_sync(0xffffffffu, sh, 16);   // combine the two K-halves

    float v    = sh * ee;
    float pnew = (m > 0.5f) ? v : pc;             // masked step keeps alphas unchanged

    if (PUBLISH) {
        unsigned mx = __reduce_max_sync(0xffffffffu, __float_as_uint(pnew));
        if (lane == 0) red_sm[w] = __uint_as_float(mx);
    }

    buf ^= 1;
    if (h == 0) p_sm[buf][pidx] = pnew;           // one writer per column
    pcur = pnew;
    __syncthreads();                              // publishes p_sm AND red_sm together
}

__global__ void __launch_bounds__(NT, 1) crf_kernel(
    const float* __restrict__ em, const float* __restrict__ trans,
    const float* __restrict__ mask, const int* __restrict__ tags,
    float* __restrict__ out)
{
    __shared__ __align__(16) float p_sm[2][PPAD];
    __shared__ float msk_sm[CRF_S];
    __shared__ float red_sm[8];
    __shared__ float red2_sm[16];

    const int tid  = threadIdx.x;
    const int b    = blockIdx.x;
    const int lane = tid & 31;
    const int w    = tid >> 5;               // 8 warps
    const int j    = (w << 4) + (lane & 15); // column owned by this thread
    const int h    = lane >> 4;              // K-half: i in [64h, 64h+64)
    const int pidx = j + ((j >> 6) << 2);    // padded p index
    const float* emb = em + (size_t)b * CRF_S * CRF_T;

    // ---- E half-column in registers: 32 packed f32x2 (i in [64h, 64h+64)) ----
    u64 Ereg[32];
#pragma unroll
    for (int k = 0; k < 32; ++k) {
        int i0 = (h << 6) + 2 * k;
        float a = __expf(trans[(i0 + 0) * CRF_T + j]);
        float c = __expf(trans[(i0 + 1) * CRF_T + j]);
        Ereg[k] = pack2(a, c);
    }

    for (int s = tid; s < CRF_S; s += NT) msk_sm[s] = mask[b * CRF_S + s];
    if (tid < 8) red_sm[tid] = 1.0f;         // identity renorm for the first apply

    // ---- alpha_0 in exp domain ----
    float pcur = __expf(trans[CRF_SOS * CRF_T + j] + emb[j]);
    if (h == 0) p_sm[0][pidx] = pcur;

    // ---- emission register pipeline: eexp ready rows 1..4, raw in flight 5..8 ----
    float eexp[4], eraw[4];
#pragma unroll
    for (int u = 0; u < 4; ++u) eexp[u] = __expf(emb[(1 + u) * CRF_T + j]);
#pragma unroll
    for (int u = 0; u < 4; ++u) eraw[u] = emb[(5 + u) * CRF_T + j];

    float Ccum = 0.0f;
    int buf = 0;
    __syncthreads();

    // ---- main scan: 255 blocks of 4 steps cover t = 1..1020 ----
    for (int blk = 0; blk < (CRF_S - 4) / 4; ++blk) {
        const int t0 = 1 + blk * 4;

        float m0 = msk_sm[t0 + 0], m1 = msk_sm[t0 + 1];
        float m2 = msk_sm[t0 + 2], m3 = msk_sm[t0 + 3];

        float enew[4];
#pragma unroll
        for (int u = 0; u < 4; ++u) enew[u] = eraw[u];     // rows t0+4..t0+7 (arrived)
#pragma unroll
        for (int u = 0; u < 4; ++u) {                      // issue rows t0+8..t0+11
            int r = t0 + 8 + u;
            eraw[u] = (r < CRF_S) ? emb[r * CRF_T + j] : 0.0f;
        }

        crf_step<true,  false>(p_sm, red_sm, Ereg, buf, pcur, Ccum, eexp[0], m0, pidx, h, w, lane);
        crf_step<false, false>(p_sm, red_sm, Ereg, buf, pcur, Ccum, eexp[1], m1, pidx, h, w, lane);
        crf_step<false, false>(p_sm, red_sm, Ereg, buf, pcur, Ccum, eexp[2], m2, pidx, h, w, lane);
        crf_step<false, true >(p_sm, red_sm, Ereg, buf, pcur, Ccum, eexp[3], m3, pidx, h, w, lane);

#pragma unroll
        for (int u = 0; u < 4; ++u) eexp[u] = __expf(enew[u]);   // off-chain convert
    }

    // ---- epilogue: t = 1021..1023 ----
    crf_step<true,  false>(p_sm, red_sm, Ereg, buf, pcur, Ccum, eexp[0], msk_sm[CRF_S - 3], pidx, h, w, lane);
    crf_step<false, false>(p_sm, red_sm, Ereg, buf, pcur, Ccum, eexp[1], msk_sm[CRF_S - 2], pidx, h, w, lane);
    crf_step<false, false>(p_sm, red_sm, Ereg, buf, pcur, Ccum, eexp[2], msk_sm[CRF_S - 1], pidx, h, w, lane);

    // ---- partition = Ccum + log( sum_j p_j * exp(T[j, EOS]) ) ----
    float vterm = (h == 0) ? pcur * __expf(trans[j * CRF_T + CRF_EOS]) : 0.0f;
#pragma unroll
    for (int off = 16; off; off >>= 1)
        vterm += __shfl_xor_sync(0xffffffffu, vterm, off);
    if (lane == 0) red_sm[w] = vterm;
    __syncthreads();
    float Z = red_sm[0] + red_sm[1] + red_sm[2] + red_sm[3]
            + red_sm[4] + red_sm[5] + red_sm[6] + red_sm[7];
    float partition = Ccum + __logf(Z);
    __syncthreads();

    // ---- gold-path score ----
    const int* tg = tags + b * CRF_S;
    float sc  = 0.0f;
    float nvf = 0.0f;
    for (int s = tid; s < CRF_S; s += NT) {
        nvf += msk_sm[s];
        if (s == 0) {
            int t0g = tg[0];
            sc += trans[CRF_SOS * CRF_T + t0g] + emb[t0g];
        } else {
            int tc = tg[s], tp = tg[s - 1];
            sc += msk_sm[s] * (emb[s * CRF_T + tc] + trans[tp * CRF_T + tc]);
        }
    }
#pragma unroll
    for (int off = 16; off; off >>= 1) {
        sc  += __shfl_xor_sync(0xffffffffu, sc, off);
        nvf += __shfl_xor_sync(0xffffffffu, nvf, off);
    }
    if (lane == 0) { red2_sm[w] = sc; red2_sm[8 + w] = nvf; }
    __syncthreads();
    float SC = 0.0f, NV = 0.0f;
#pragma unroll
    for (int r = 0; r < 8; ++r) { SC += red2_sm[r]; NV += red2_sm[8 + r]; }
    int last = (int)(NV + 0.5f) - 1;
    SC += trans[tg[last] * CRF_T + CRF_EOS];

    // ---- last-CTA-done final reduction (deterministic fixed-order sum) ----
    if (tid == 0) {
        g_part[b] = partition - SC;
        __threadfence();
        if (atomicAdd(&g_count, 1) == CRF_B - 1) {
            __threadfence();
            float s = 0.0f;
#pragma unroll 8
            for (int k = 0; k < CRF_B; ++k) s += g_part[k];
            out[0] = s;
            g_count = 0;            // reset for the next graph replay
            __threadfence();
        }
    }
}

extern "C" void kernel_launch(void* const* d_in, const int* in_sizes, int n_in,
                              void* d_out, int out_size) {
    const float* em = (const float*)d_in[0];   // emissions (B,S,T) f32
    const float* tr = (const float*)d_in[1];   // transition (T,T)  f32
    const float* mk = (const float*)d_in[2];   // mask (B,S)        f32
    const int*   tg = (const int*)d_in[3];     // tags (B,S)        i32

    crf_kernel<<<CRF_B, NT>>>(em, tr, mk, tg, (float*)d_out);
}